// round 1
// baseline (speedup 1.0000x reference)
#include <cuda_runtime.h>
#include <math.h>

#define HNUM 512
#define WNUM 512
#define NIMG 12                       // N*C = 4*3
#define NPIX (NIMG*HNUM*WNUM)         // 3145728
#define WSTRIDE 168                   // padded weight stride (>= Kmax + 8)

// ---- scratch (static device memory; no allocations allowed) ----
__device__ float  d_diff[NPIX];
__device__ float  d_A[NPIX];
__device__ float  d_B[NPIX];
__device__ float  d_S[NPIX];
__device__ float  d_gw[6*WSTRIDE];
__device__ float  d_uw[6*WSTRIDE];
__device__ float  d_c[6];
__device__ double d_acc;

__device__ __forceinline__ int refl(int t){
    int r = t < 0 ? -t : t;
    return r >= HNUM ? (2*HNUM - 2 - r) : r;
}

// ---- init: compute separable LoG weights + mean-subtraction constant ----
__global__ void init_kernel(){
    const float sig[6] = {0.6f, 1.2f, 2.4f, 4.8f, 9.6f, 19.2f};
    const int   ks [6] = {5, 11, 21, 39, 77, 155};
    if (threadIdx.x == 0) d_acc = 0.0;
    for (int s = 0; s < 6; ++s){
        int K = ks[s];
        float ss = sig[s]*sig[s];
        float sn = 0.3989422804014327f / ss;   // sqrt(1/(2*pi*ss^2)) = 1/(ss*sqrt(2pi))
        int half = K/2;
        for (int j = threadIdx.x; j < WSTRIDE; j += blockDim.x){
            float g = 0.f, u = 0.f;
            if (j < K){
                float t  = (float)(j - half);
                float t2 = t*t;
                float e  = expf(-t2 / (2.f*ss));
                g = e * sn;
                u = (t2 - ss) * e * sn;
            }
            d_gw[s*WSTRIDE + j] = g;
            d_uw[s*WSTRIDE + j] = u;
        }
    }
    __syncthreads();
    if (threadIdx.x == 0){
        for (int s = 0; s < 6; ++s){
            int K = ks[s];
            double sg = 0.0, su = 0.0;
            for (int j = 0; j < K; ++j){
                sg += (double)d_gw[s*WSTRIDE + j];
                su += (double)d_uw[s*WSTRIDE + j];
            }
            // a_raw.sum()/K^2 = 2*(sum gw)*(sum uw)/K^2   (norm already folded in)
            d_c[s] = (float)(2.0 * sg * su / ((double)K * (double)K));
        }
    }
}

// ---- diff = input - target ----
__global__ void diff_kernel(const float4* __restrict__ a, const float4* __restrict__ b){
    int i = blockIdx.x*blockDim.x + threadIdx.x;
    if (i < NPIX/4){
        float4 x = a[i], y = b[i];
        float4 d = make_float4(x.x-y.x, x.y-y.y, x.z-y.z, x.w-y.w);
        reinterpret_cast<float4*>(d_diff)[i] = d;
    }
}

// ---- horizontal pass: conv along W with reflect pad.
// Writes A = G-conv(diff), B = U-conv(diff), S = box-conv(diff).
// 128 threads, 4 consecutive outputs per thread, rolling zero-padded weight windows.
template<int K>
__global__ void __launch_bounds__(128) hpass_kernel(int s)
{
    constexpr int P     = K/2;
    constexpr int TS    = WNUM + K - 1;
    constexpr int STEPS = K + 3;
    __shared__ float  tile[TS];
    __shared__ float2 wsm[STEPS];

    const int    row   = blockIdx.x;
    const size_t ibase = ((size_t)blockIdx.y * HNUM + row) * WNUM;
    const float* src   = d_diff + ibase;
    const float* gw    = d_gw + s*WSTRIDE;
    const float* uw    = d_uw + s*WSTRIDE;

    for (int i = threadIdx.x; i < TS; i += 128) tile[i] = src[refl(i - P)];
    for (int j = threadIdx.x; j < STEPS; j += 128) wsm[j] = make_float2(gw[j], uw[j]);
    __syncthreads();

    const int w0 = threadIdx.x * 4;
    float a[4]  = {0,0,0,0}, b[4]  = {0,0,0,0}, sb[4] = {0,0,0,0};
    float wg[4] = {0,0,0,0}, wu[4] = {0,0,0,0}, wx[4] = {0,0,0,0};

#pragma unroll 4
    for (int t = 0; t < STEPS; ++t){
#pragma unroll
        for (int r = 3; r > 0; --r){ wg[r]=wg[r-1]; wu[r]=wu[r-1]; wx[r]=wx[r-1]; }
        float2 wp = wsm[t];
        wg[0] = wp.x; wu[0] = wp.y; wx[0] = (t < K) ? 1.f : 0.f;
        float v = tile[w0 + t];
#pragma unroll
        for (int r = 0; r < 4; ++r){
            a[r]  += wg[r]*v;
            b[r]  += wu[r]*v;
            sb[r] += wx[r]*v;
        }
    }
    size_t o = ibase + w0;
    *(float4*)(d_A + o) = make_float4(a[0],  a[1],  a[2],  a[3]);
    *(float4*)(d_B + o) = make_float4(b[0],  b[1],  b[2],  b[3]);
    *(float4*)(d_S + o) = make_float4(sb[0], sb[1], sb[2], sb[3]);
}

// ---- vertical pass phase: accumulate conv of `src` along H into o[8] ----
template<int K, bool BOX>
__device__ __forceinline__ void vphase(const float* __restrict__ src,
    size_t ibase, int h0, int gcol0, int tid, int tx, int rb,
    float (* __restrict__ tile)[32], float* __restrict__ wsm,
    const float* __restrict__ wg, float cw, float (&o)[8])
{
    constexpr int P = K/2, TR = 64 + K - 1, STEPS = K + 7;
    for (int i = tid; i < TR*32; i += 256){
        int r = i >> 5, cc = i & 31;
        tile[r][cc] = src[ibase + (size_t)refl(h0 + r - P)*WNUM + (gcol0 + cc)];
    }
    for (int j = tid; j < STEPS; j += 256)
        wsm[j] = BOX ? ((j < K) ? cw : 0.f) : wg[j];   // wg zero-padded beyond K
    __syncthreads();

    float w[8];
#pragma unroll
    for (int r = 0; r < 8; ++r) w[r] = 0.f;
#pragma unroll 8
    for (int t = 0; t < STEPS; ++t){
#pragma unroll
        for (int r = 7; r > 0; --r) w[r] = w[r-1];
        w[0] = wsm[t];
        float v = tile[rb + t][tx];
#pragma unroll
        for (int r = 0; r < 8; ++r) o[r] += w[r]*v;
    }
    __syncthreads();
}

// ---- vertical pass: out = U-conv(A) + G-conv(B) - c*box(S); reduce w*out^2 ----
template<int K>
__global__ void __launch_bounds__(256) vpass_kernel(int s, float wloss)
{
    constexpr int TR = 64 + K - 1, STEPS = K + 7;
    __shared__ float tile[TR][32];
    __shared__ float wsm[STEPS];
    __shared__ float wred[8];

    const int tx = threadIdx.x, ty = threadIdx.y;
    const int tid = ty*32 + tx;
    const int h0 = blockIdx.y * 64;
    const int gcol0 = blockIdx.x * 32;
    const size_t ibase = (size_t)blockIdx.z * (HNUM*WNUM);
    const int rb = ty*8;

    float o[8];
#pragma unroll
    for (int r = 0; r < 8; ++r) o[r] = 0.f;

    const float* uw = d_uw + s*WSTRIDE;
    const float* gw = d_gw + s*WSTRIDE;
    float cneg = -d_c[s];

    vphase<K,false>(d_A, ibase, h0, gcol0, tid, tx, rb, tile, wsm, uw, 0.f,  o);
    vphase<K,false>(d_B, ibase, h0, gcol0, tid, tx, rb, tile, wsm, gw, 0.f,  o);
    vphase<K,true >(d_S, ibase, h0, gcol0, tid, tx, rb, tile, wsm, gw, cneg, o);

    float ls = 0.f;
#pragma unroll
    for (int r = 0; r < 8; ++r) ls += o[r]*o[r];
#pragma unroll
    for (int off = 16; off; off >>= 1) ls += __shfl_down_sync(0xffffffffu, ls, off);
    if (tx == 0) wred[ty] = ls;
    __syncthreads();
    if (tid == 0){
        double t = 0.0;
#pragma unroll
        for (int i = 0; i < 8; ++i) t += (double)wred[i];
        atomicAdd(&d_acc, t * (double)wloss);
    }
}

// ---- finalize ----
__global__ void final_kernel(float* out){
    out[0] = (float)(d_acc * (1.0 / (double)NPIX));
}

extern "C" void kernel_launch(void* const* d_in, const int* in_sizes, int n_in,
                              void* d_out, int out_size)
{
    const float4* input  = (const float4*)d_in[0];
    const float4* target = (const float4*)d_in[1];
    float* out = (float*)d_out;

    init_kernel<<<1, 256>>>();
    diff_kernel<<<(NPIX/4 + 255)/256, 256>>>(input, target);

    const dim3 hgrid(512, NIMG);
    const dim3 vgrid(16, 8, NIMG);
    const dim3 vblk(32, 8);

    hpass_kernel<5  ><<<hgrid, 128>>>(0);
    vpass_kernel<5  ><<<vgrid, vblk>>>(0, 600.f);
    hpass_kernel<11 ><<<hgrid, 128>>>(1);
    vpass_kernel<11 ><<<vgrid, vblk>>>(1, 500.f);
    hpass_kernel<21 ><<<hgrid, 128>>>(2);
    vpass_kernel<21 ><<<vgrid, vblk>>>(2, 400.f);
    hpass_kernel<39 ><<<hgrid, 128>>>(3);
    vpass_kernel<39 ><<<vgrid, vblk>>>(3, 20.f);
    hpass_kernel<77 ><<<hgrid, 128>>>(4);
    vpass_kernel<77 ><<<vgrid, vblk>>>(4, 10.f);
    hpass_kernel<155><<<hgrid, 128>>>(5);
    vpass_kernel<155><<<vgrid, vblk>>>(5, 10.f);

    final_kernel<<<1, 1>>>(out);
}

// round 2
// speedup vs baseline: 1.0349x; 1.0349x over previous
#include <cuda_runtime.h>
#include <math.h>

#define HNUM 512
#define WNUM 512
#define NIMG 12
#define NPIX (NIMG*HNUM*WNUM)
#define WSTRIDE 176

typedef unsigned long long ull;

// ---- scratch (static device memory) ----
__device__ float  d_diff[NPIX];
__device__ ull    d_AB[NPIX];     // interleaved {A = G*diff, B = U*diff} along W
__device__ float  d_S[NPIX];      // box*diff along W
__device__ float  d_gw[6*WSTRIDE];
__device__ float  d_uw[6*WSTRIDE];
__device__ float  d_c[6];
__device__ double d_accv[64];

__device__ __forceinline__ int refl(int t){
    int r = t < 0 ? -t : t;
    return r >= HNUM ? (2*HNUM - 2 - r) : r;
}
__device__ __forceinline__ ull pk(float x, float y){
    ull r; asm("mov.b64 %0,{%1,%2};" : "=l"(r) : "f"(x), "f"(y)); return r;
}
__device__ __forceinline__ void upk(ull v, float& x, float& y){
    asm("mov.b64 {%0,%1},%2;" : "=f"(x), "=f"(y) : "l"(v));
}
__device__ __forceinline__ void fma2(ull& d, ull a, ull b){
    asm("fma.rn.f32x2 %0,%1,%2,%0;" : "+l"(d) : "l"(a), "l"(b));
}

// ---- init: separable LoG weights + mean constant; zero accumulators ----
__global__ void init_kernel(){
    const float sig[6] = {0.6f, 1.2f, 2.4f, 4.8f, 9.6f, 19.2f};
    const int   ks [6] = {5, 11, 21, 39, 77, 155};
    if (threadIdx.x < 64) d_accv[threadIdx.x] = 0.0;
    for (int s = 0; s < 6; ++s){
        int K = ks[s];
        float ss = sig[s]*sig[s];
        float sn = 0.3989422804014327f / ss;   // 1/(ss*sqrt(2pi))
        int half = K/2;
        for (int j = threadIdx.x; j < WSTRIDE; j += blockDim.x){
            float g = 0.f, u = 0.f;
            if (j < K){
                float t  = (float)(j - half);
                float t2 = t*t;
                float e  = expf(-t2 / (2.f*ss));
                g = e * sn;
                u = (t2 - ss) * e * sn;
            }
            d_gw[s*WSTRIDE + j] = g;
            d_uw[s*WSTRIDE + j] = u;
        }
    }
    __syncthreads();
    if (threadIdx.x == 0){
        for (int s = 0; s < 6; ++s){
            int K = ks[s];
            double sg = 0.0, su = 0.0;
            for (int j = 0; j < K; ++j){
                sg += (double)d_gw[s*WSTRIDE + j];
                su += (double)d_uw[s*WSTRIDE + j];
            }
            d_c[s] = (float)(2.0 * sg * su / ((double)K * (double)K));
        }
    }
}

// ---- diff = input - target ----
__global__ void diff_kernel(const float4* __restrict__ a, const float4* __restrict__ b){
    int i = blockIdx.x*blockDim.x + threadIdx.x;
    if (i < NPIX/4){
        float4 x = a[i], y = b[i];
        reinterpret_cast<float4*>(d_diff)[i] =
            make_float4(x.x-y.x, x.y-y.y, x.z-y.z, x.w-y.w);
    }
}

// ---- horizontal pass: 4 rows x 512 cols per block; thread = 4 cols x 4 rows.
// f32x2 packs row pairs. Rolling weights via 4-slot rotation (no shifts).
template<int K>
__global__ void __launch_bounds__(128) hpass_kernel(int s)
{
    constexpr int P   = K/2;
    constexpr int SH  = ((K + 3 + 3)/4)*4;   // steps, mult of 4, >= K+3
    constexpr int TS  = 508 + SH;
    constexpr int TSP = TS + TS/8 + 2;       // swizzle-padded
    __shared__ __align__(16) ulonglong2 tile[TSP];   // {rows01, rows23}
    __shared__ __align__(16) ulonglong2 wgu[SH];     // {{g,g},{u,u}}
    __shared__ ull wb[SH];                           // {b,b}

    const int tx = threadIdx.x;
    const int r0 = blockIdx.x*4;
    const size_t base = ((size_t)blockIdx.y*HNUM + r0)*WNUM;
    const float* src = d_diff + base;
    const float* gwp = d_gw + s*WSTRIDE;
    const float* uwp = d_uw + s*WSTRIDE;

    for (int u = tx; u < TS; u += 128){
        int c = refl(u - P);
        float v0 = src[c], v1 = src[c+WNUM], v2 = src[c+2*WNUM], v3 = src[c+3*WNUM];
        tile[u + (u>>3)] = make_ulonglong2(pk(v0,v1), pk(v2,v3));
    }
    for (int t = tx; t < SH; t += 128){
        float g = gwp[t], u_ = uwp[t];
        wgu[t] = make_ulonglong2(pk(g,g), pk(u_,u_));
        float b = (t < K) ? 1.f : 0.f;
        wb[t]  = pk(b,b);
    }
    __syncthreads();

    ull aG01[4], aG23[4], aU01[4], aU23[4], aS01[4], aS23[4];
    ull wgg[4], wuu[4], wbb[4];
#pragma unroll
    for (int r = 0; r < 4; ++r){
        aG01[r]=0; aG23[r]=0; aU01[r]=0; aU23[r]=0; aS01[r]=0; aS23[r]=0;
        wgg[r]=0; wuu[r]=0; wbb[r]=0;
    }

    const int w0 = tx*4;
    for (int t0 = 0; t0 < SH; t0 += 4){
#pragma unroll
        for (int j = 0; j < 4; ++j){
            int t = t0 + j;
            ulonglong2 w = wgu[t];
            wgg[j] = w.x; wuu[j] = w.y; wbb[j] = wb[t];
            int u = w0 + t;
            ulonglong2 v = tile[u + (u>>3)];
#pragma unroll
            for (int r = 0; r < 4; ++r){
                const int sl = (j - r) & 3;
                fma2(aG01[r], wgg[sl], v.x);
                fma2(aG23[r], wgg[sl], v.y);
                fma2(aU01[r], wuu[sl], v.x);
                fma2(aU23[r], wuu[sl], v.y);
                fma2(aS01[r], wbb[sl], v.x);
                fma2(aS23[r], wbb[sl], v.y);
            }
        }
    }

#pragma unroll
    for (int r = 0; r < 4; ++r){
        float a0,a1,a2,a3,b0,b1,b2,b3,x0,x1,x2,x3;
        upk(aG01[r],a0,a1); upk(aG23[r],a2,a3);
        upk(aU01[r],b0,b1); upk(aU23[r],b2,b3);
        upk(aS01[r],x0,x1); upk(aS23[r],x2,x3);
        size_t o = base + (w0 + r);
        d_AB[o         ] = pk(a0,b0);
        d_AB[o +   WNUM] = pk(a1,b1);
        d_AB[o + 2*WNUM] = pk(a2,b2);
        d_AB[o + 3*WNUM] = pk(a3,b3);
        d_S[o] = x0; d_S[o+WNUM] = x1; d_S[o+2*WNUM] = x2; d_S[o+3*WNUM] = x3;
    }
}

// ---- vertical pass: 16 cols x 128 rows per block; thread = 2 cols x 8 rows.
// Phase 1: interleaved {A,B} * {u,g}; Phase 2: S * (-c box). 8-slot rotation.
template<int K>
__global__ void __launch_bounds__(128) vpass_kernel(int s, float wloss)
{
    constexpr int P  = K/2;
    constexpr int SV = ((K + 7 + 7)/8)*8;    // steps, mult of 8, >= K+7
    constexpr int TR = 120 + SV;
    __shared__ __align__(16) ull tile[TR*16];
    __shared__ ull wab[SV];
    __shared__ ull wsb[SV];
    __shared__ float wred[4];

    const int tx = threadIdx.x;       // 0..7
    const int ty = threadIdx.y;       // 0..15
    const int tid = ty*8 + tx;
    const int col0 = blockIdx.x*16;
    const int h0   = blockIdx.y*128;
    const size_t ibase = (size_t)blockIdx.z*(HNUM*WNUM);
    const int rb = ty*8;

    const float* uwp = d_uw + s*WSTRIDE;
    const float* gwp = d_gw + s*WSTRIDE;
    const float cn = -d_c[s];
    for (int t = tid; t < SV; t += 128){
        wab[t] = pk(uwp[t], gwp[t]);          // A gets U-weight, B gets G-weight
        float b = (t < K) ? cn : 0.f;
        wsb[t] = pk(b,b);
    }
    for (int i = tid; i < TR*16; i += 128){
        int r = i >> 4, cc = i & 15;
        tile[i] = d_AB[ibase + (size_t)refl(h0 + r - P)*WNUM + (col0 + cc)];
    }
    __syncthreads();

    ull accA[8], accB[8], w2[8];
#pragma unroll
    for (int r = 0; r < 8; ++r){ accA[r]=0; accB[r]=0; w2[r]=0; }

    for (int t0 = 0; t0 < SV; t0 += 8){
#pragma unroll
        for (int j = 0; j < 8; ++j){
            int t = t0 + j;
            w2[j] = wab[t];
            ulonglong2 v = *(const ulonglong2*)&tile[(rb + t)*16 + 2*tx];
#pragma unroll
            for (int r = 0; r < 8; ++r){
                const int sl = (j - r) & 7;
                fma2(accA[r], w2[sl], v.x);
                fma2(accB[r], w2[sl], v.y);
            }
        }
    }
    __syncthreads();

    // Phase 2: S box (tile reused as [TR][8] of packed col-pairs)
    ull* tileS = tile;
    for (int i = tid; i < TR*8; i += 128){
        int r = i >> 3, cc = i & 7;
        tileS[i] = *(const ull*)&d_S[ibase + (size_t)refl(h0 + r - P)*WNUM + (col0 + 2*cc)];
    }
    __syncthreads();

    ull accS[8];
#pragma unroll
    for (int r = 0; r < 8; ++r){ accS[r]=0; w2[r]=0; }

    for (int t0 = 0; t0 < SV; t0 += 8){
#pragma unroll
        for (int j = 0; j < 8; ++j){
            int t = t0 + j;
            w2[j] = wsb[t];
            ull v = tileS[(rb + t)*8 + tx];
#pragma unroll
            for (int r = 0; r < 8; ++r){
                fma2(accS[r], w2[(j - r) & 7], v);
            }
        }
    }

    float ls = 0.f;
#pragma unroll
    for (int r = 0; r < 8; ++r){
        float p, q, o0, o1, s0, s1;
        upk(accA[r], p, q); o0 = p + q;
        upk(accB[r], p, q); o1 = p + q;
        upk(accS[r], s0, s1);
        o0 += s0; o1 += s1;
        ls += o0*o0 + o1*o1;
    }
#pragma unroll
    for (int off = 16; off; off >>= 1) ls += __shfl_down_sync(0xffffffffu, ls, off);
    if ((tid & 31) == 0) wred[tid >> 5] = ls;
    __syncthreads();
    if (tid == 0){
        float tot = wred[0] + wred[1] + wred[2] + wred[3];
        int slot = (blockIdx.x + blockIdx.y*32 + blockIdx.z*5) & 63;
        atomicAdd(&d_accv[slot], (double)tot * (double)wloss);
    }
}

// ---- finalize ----
__global__ void final_kernel(float* out){
    double t = 0.0;
#pragma unroll
    for (int i = 0; i < 64; ++i) t += d_accv[i];
    out[0] = (float)(t * (1.0 / (double)NPIX));
}

extern "C" void kernel_launch(void* const* d_in, const int* in_sizes, int n_in,
                              void* d_out, int out_size)
{
    const float4* input  = (const float4*)d_in[0];
    const float4* target = (const float4*)d_in[1];
    float* out = (float*)d_out;

    init_kernel<<<1, 256>>>();
    diff_kernel<<<(NPIX/4 + 255)/256, 256>>>(input, target);

    const dim3 hgrid(128, NIMG);
    const dim3 vgrid(32, 4, NIMG);
    const dim3 vblk(8, 16);

    hpass_kernel<5  ><<<hgrid, 128>>>(0);
    vpass_kernel<5  ><<<vgrid, vblk>>>(0, 600.f);
    hpass_kernel<11 ><<<hgrid, 128>>>(1);
    vpass_kernel<11 ><<<vgrid, vblk>>>(1, 500.f);
    hpass_kernel<21 ><<<hgrid, 128>>>(2);
    vpass_kernel<21 ><<<vgrid, vblk>>>(2, 400.f);
    hpass_kernel<39 ><<<hgrid, 128>>>(3);
    vpass_kernel<39 ><<<vgrid, vblk>>>(3, 20.f);
    hpass_kernel<77 ><<<hgrid, 128>>>(4);
    vpass_kernel<77 ><<<vgrid, vblk>>>(4, 10.f);
    hpass_kernel<155><<<hgrid, 128>>>(5);
    vpass_kernel<155><<<vgrid, vblk>>>(5, 10.f);

    final_kernel<<<1, 1>>>(out);
}

// round 3
// speedup vs baseline: 1.3275x; 1.2828x over previous
#include <cuda_runtime.h>
#include <math.h>

#define HNUM 512
#define WNUM 512
#define NIMG 12
#define NPIX (NIMG*HNUM*WNUM)
#define WSTRIDE 176

typedef unsigned long long ull;

// ---- scratch (static device memory) ----
__device__ float  d_diff[NPIX];
__device__ ull    d_AB[(size_t)6*NPIX];   // per-sigma interleaved {A=G*d, B=U*d} along W
__device__ float  d_S[(size_t)6*NPIX];    // per-sigma box*d along W (from prefix sums)
__device__ float  d_gw[6*WSTRIDE];
__device__ float  d_uw[6*WSTRIDE];
__device__ float  d_c[6];
__device__ double d_accv[64];

__device__ __forceinline__ int refl(int t){
    int r = t < 0 ? -t : t;
    return r >= HNUM ? (2*HNUM - 2 - r) : r;
}
__device__ __forceinline__ ull pk(float x, float y){
    ull r; asm("mov.b64 %0,{%1,%2};" : "=l"(r) : "f"(x), "f"(y)); return r;
}
__device__ __forceinline__ void upk(ull v, float& x, float& y){
    asm("mov.b64 {%0,%1},%2;" : "=f"(x), "=f"(y) : "l"(v));
}
__device__ __forceinline__ void fma2(ull& d, ull a, ull b){
    asm("fma.rn.f32x2 %0,%1,%2,%0;" : "+l"(d) : "l"(a), "l"(b));
}
__device__ __forceinline__ void add2(ull& d, ull a){
    asm("add.rn.f32x2 %0,%0,%1;" : "+l"(d) : "l"(a));
}

// ---- init: separable LoG weights + mean constant; zero accumulators ----
__global__ void init_kernel(){
    const float sig[6] = {0.6f, 1.2f, 2.4f, 4.8f, 9.6f, 19.2f};
    const int   ks [6] = {5, 11, 21, 39, 77, 155};
    if (threadIdx.x < 64) d_accv[threadIdx.x] = 0.0;
    for (int s = 0; s < 6; ++s){
        int K = ks[s];
        float ss = sig[s]*sig[s];
        float sn = 0.3989422804014327f / ss;   // 1/(ss*sqrt(2pi))
        int half = K/2;
        for (int j = threadIdx.x; j < WSTRIDE; j += blockDim.x){
            float g = 0.f, u = 0.f;
            if (j < K){
                float t  = (float)(j - half);
                float t2 = t*t;
                float e  = expf(-t2 / (2.f*ss));
                g = e * sn;
                u = (t2 - ss) * e * sn;
            }
            d_gw[s*WSTRIDE + j] = g;
            d_uw[s*WSTRIDE + j] = u;
        }
    }
    __syncthreads();
    if (threadIdx.x == 0){
        for (int s = 0; s < 6; ++s){
            int K = ks[s];
            double sg = 0.0, su = 0.0;
            for (int j = 0; j < K; ++j){
                sg += (double)d_gw[s*WSTRIDE + j];
                su += (double)d_uw[s*WSTRIDE + j];
            }
            d_c[s] = (float)(2.0 * sg * su / ((double)K * (double)K));
        }
    }
}

// ---- fused diff + per-row prefix + box outputs for all 6 sigmas ----
// One block per (row, img). diff stored for hpass; box-along-W via prefix diffs.
__global__ void __launch_bounds__(256) diff_prefix_kernel(
    const float* __restrict__ in, const float* __restrict__ tg)
{
    __shared__ float dr[512];
    __shared__ float q[667];      // exclusive prefix over padded row (pad 77 each side)
    __shared__ float wsum[8];

    const int row = blockIdx.x, img = blockIdx.y;
    const size_t base = ((size_t)img*HNUM + row)*WNUM;
    const int tid = threadIdx.x;

    for (int x = tid; x < 512; x += 256){
        float d = in[base+x] - tg[base+x];
        dr[x] = d;
        d_diff[base+x] = d;
    }
    __syncthreads();

    // padded values p[i] = dr[refl(i-77)], i in [0,666)
    const int i0 = tid*3;
    float v0 = (i0   < 666) ? dr[refl(i0-77)]   : 0.f;
    float v1 = (i0+1 < 666) ? dr[refl(i0-76)]   : 0.f;
    float v2 = (i0+2 < 666) ? dr[refl(i0-75)]   : 0.f;
    float s01 = v0 + v1;
    float tot = s01 + v2;

    // warp inclusive scan of per-thread totals
    float inc = tot;
#pragma unroll
    for (int off = 1; off < 32; off <<= 1){
        float n = __shfl_up_sync(0xffffffffu, inc, off);
        if ((tid & 31) >= off) inc += n;
    }
    if ((tid & 31) == 31) wsum[tid >> 5] = inc;
    __syncthreads();
    if (tid == 0){
        float a = 0.f;
#pragma unroll
        for (int i = 0; i < 8; ++i){ float t = wsum[i]; wsum[i] = a; a += t; }
    }
    __syncthreads();
    float ex = inc - tot + wsum[tid >> 5];   // exclusive prefix at chunk start
    if (i0   <= 666) q[i0]   = ex;
    if (i0+1 <= 666) q[i0+1] = ex + v0;
    if (i0+2 <= 666) q[i0+2] = ex + s01;
    __syncthreads();

    const int KS[6] = {5, 11, 21, 39, 77, 155};
#pragma unroll
    for (int s = 0; s < 6; ++s){
        int K = KS[s], P = K >> 1;
        for (int x = tid; x < 512; x += 256){
            int lo = x + 77 - P;
            d_S[(size_t)s*NPIX + base + x] = q[lo + K] - q[lo];
        }
    }
}

// ---- horizontal pass core: 4 rows x 512 cols per block; thread = 4 cols x 4 rows.
// f32x2 packs row pairs. G,U streams only (box comes from prefix kernel).
template<int K>
__device__ __forceinline__ void hpass_core(int s, int img, char* smraw)
{
    constexpr int P   = K/2;
    constexpr int SH  = ((K + 3 + 3)/4)*4;
    constexpr int TS  = 508 + SH;
    constexpr int TSP = TS + TS/8 + 2;
    ulonglong2* tile = (ulonglong2*)smraw;
    ulonglong2* wgu  = (ulonglong2*)(smraw + (size_t)TSP*sizeof(ulonglong2));

    const int tx = threadIdx.x;
    const int r0 = blockIdx.x*4;
    const size_t base = ((size_t)img*HNUM + r0)*WNUM;
    const float* src = d_diff + base;
    const float* gwp = d_gw + s*WSTRIDE;
    const float* uwp = d_uw + s*WSTRIDE;

    for (int u = tx; u < TS; u += 128){
        int c = refl(u - P);
        float v0 = src[c], v1 = src[c+WNUM], v2 = src[c+2*WNUM], v3 = src[c+3*WNUM];
        tile[u + (u>>3)] = make_ulonglong2(pk(v0,v1), pk(v2,v3));
    }
    for (int t = tx; t < SH; t += 128){
        float g = gwp[t], u_ = uwp[t];
        wgu[t] = make_ulonglong2(pk(g,g), pk(u_,u_));
    }
    __syncthreads();

    ull aG01[4], aG23[4], aU01[4], aU23[4], wgg[4], wuu[4];
#pragma unroll
    for (int r = 0; r < 4; ++r){
        aG01[r]=0; aG23[r]=0; aU01[r]=0; aU23[r]=0; wgg[r]=0; wuu[r]=0;
    }

    const int w0 = tx*4;
    for (int t0 = 0; t0 < SH; t0 += 4){
#pragma unroll
        for (int j = 0; j < 4; ++j){
            int t = t0 + j;
            ulonglong2 w = wgu[t];
            wgg[j] = w.x; wuu[j] = w.y;
            int u = w0 + t;
            ulonglong2 v = tile[u + (u>>3)];
#pragma unroll
            for (int r = 0; r < 4; ++r){
                const int sl = (j - r) & 3;
                fma2(aG01[r], wgg[sl], v.x);
                fma2(aG23[r], wgg[sl], v.y);
                fma2(aU01[r], wuu[sl], v.x);
                fma2(aU23[r], wuu[sl], v.y);
            }
        }
    }

    // transpose to per-row and store coalesced (32B contiguous per thread per row)
    float A0[4],A1[4],A2[4],A3[4],B0[4],B1[4],B2[4],B3[4];
#pragma unroll
    for (int r = 0; r < 4; ++r){
        upk(aG01[r], A0[r], A1[r]); upk(aG23[r], A2[r], A3[r]);
        upk(aU01[r], B0[r], B1[r]); upk(aU23[r], B2[r], B3[r]);
    }
    ull* dst = d_AB + (size_t)s*NPIX + base + w0;
    *(ulonglong2*)(dst)              = make_ulonglong2(pk(A0[0],B0[0]), pk(A0[1],B0[1]));
    *(ulonglong2*)(dst+2)            = make_ulonglong2(pk(A0[2],B0[2]), pk(A0[3],B0[3]));
    *(ulonglong2*)(dst+WNUM)         = make_ulonglong2(pk(A1[0],B1[0]), pk(A1[1],B1[1]));
    *(ulonglong2*)(dst+WNUM+2)       = make_ulonglong2(pk(A1[2],B1[2]), pk(A1[3],B1[3]));
    *(ulonglong2*)(dst+2*WNUM)       = make_ulonglong2(pk(A2[0],B2[0]), pk(A2[1],B2[1]));
    *(ulonglong2*)(dst+2*WNUM+2)     = make_ulonglong2(pk(A2[2],B2[2]), pk(A2[3],B2[3]));
    *(ulonglong2*)(dst+3*WNUM)       = make_ulonglong2(pk(A3[0],B3[0]), pk(A3[1],B3[1]));
    *(ulonglong2*)(dst+3*WNUM+2)     = make_ulonglong2(pk(A3[2],B3[2]), pk(A3[3],B3[3]));
}

__global__ void __launch_bounds__(128) hpass_all()
{
    extern __shared__ char smh[];
    int z = blockIdx.z; int so = z/12; int img = z - so*12;
    switch (so){
        case 0: hpass_core<155>(5, img, smh); break;
        case 1: hpass_core<77 >(4, img, smh); break;
        case 2: hpass_core<39 >(3, img, smh); break;
        case 3: hpass_core<21 >(2, img, smh); break;
        case 4: hpass_core<11 >(1, img, smh); break;
        default:hpass_core<5  >(0, img, smh); break;
    }
}

// ---- vertical pass core: 16 cols x 128 rows per block; thread = 2 cols x 8 rows.
// Phase 1: {A,B}*{u,g} via 8-slot rotation. Phase 2: box of S via sliding window.
template<int K>
__device__ __forceinline__ void vpass_core(int s, int img, char* smraw, float wloss)
{
    constexpr int P  = K/2;
    constexpr int SV = ((K + 7 + 7)/8)*8;
    constexpr int TR = 120 + SV;
    ull*   tile = (ull*)smraw;
    ull*   wab  = (ull*)(smraw + (size_t)TR*16*8);
    float* wred = (float*)(smraw + (size_t)TR*16*8 + (size_t)SV*8);

    const int tid = threadIdx.x;
    const int tx = tid & 7, ty = tid >> 3;
    const int rb = ty*8;
    const int col0 = blockIdx.x*16;
    const int h0   = blockIdx.y*128;
    const size_t ibase = (size_t)img*(HNUM*WNUM);
    const ull*   AB = d_AB + (size_t)s*NPIX + ibase;
    const float* Sp = d_S  + (size_t)s*NPIX + ibase;

    const float* uwp = d_uw + s*WSTRIDE;
    const float* gwp = d_gw + s*WSTRIDE;
    for (int t = tid; t < SV; t += 128)
        wab[t] = pk(uwp[t], gwp[t]);          // A gets U vertically, B gets G
    for (int i = tid; i < TR*16; i += 128){
        int r = i >> 4, cc = i & 15;
        tile[i] = AB[(size_t)refl(h0 + r - P)*WNUM + (col0 + cc)];
    }
    __syncthreads();

    ull accA[8], accB[8], w2[8];
#pragma unroll
    for (int r = 0; r < 8; ++r){ accA[r]=0; accB[r]=0; w2[r]=0; }

    for (int t0 = 0; t0 < SV; t0 += 8){
#pragma unroll
        for (int j = 0; j < 8; ++j){
            int t = t0 + j;
            w2[j] = wab[t];
            ulonglong2 v = *(const ulonglong2*)&tile[(rb + t)*16 + 2*tx];
#pragma unroll
            for (int r = 0; r < 8; ++r){
                const int sl = (j - r) & 7;
                fma2(accA[r], w2[sl], v.x);
                fma2(accB[r], w2[sl], v.y);
            }
        }
    }
    __syncthreads();

    // Phase 2: sliding box over S (tile reused as [TR][8] packed col-pairs)
    ull* tileS = tile;
    for (int i = tid; i < TR*8; i += 128){
        int r = i >> 3, cc = i & 7;
        tileS[i] = *(const ull*)&Sp[(size_t)refl(h0 + r - P)*WNUM + (col0 + 2*cc)];
    }
    __syncthreads();

    ull sbox = 0;
#pragma unroll 8
    for (int t = 0; t < K; ++t) add2(sbox, tileS[(rb + t)*8 + tx]);

    const float cn = -d_c[s];
    const ull NEG1 = pk(-1.f, -1.f);
    float ls = 0.f;
#pragma unroll
    for (int r = 0; r < 8; ++r){
        if (r){
            add2(sbox, tileS[(rb + r - 1 + K)*8 + tx]);
            fma2(sbox, tileS[(rb + r - 1)*8 + tx], NEG1);
        }
        float pA,qA,pB,qB,s0,s1;
        upk(accA[r], pA, qA);
        upk(accB[r], pB, qB);
        upk(sbox, s0, s1);
        float o0 = fmaf(cn, s0, pA + qA);
        float o1 = fmaf(cn, s1, pB + qB);
        ls += o0*o0 + o1*o1;
    }
#pragma unroll
    for (int off = 16; off; off >>= 1) ls += __shfl_down_sync(0xffffffffu, ls, off);
    if ((tid & 31) == 0) wred[tid >> 5] = ls;
    __syncthreads();
    if (tid == 0){
        float tot = wred[0] + wred[1] + wred[2] + wred[3];
        int slot = (blockIdx.x + blockIdx.y*32 + blockIdx.z*7) & 63;
        atomicAdd(&d_accv[slot], (double)tot * (double)wloss);
    }
}

__global__ void __launch_bounds__(128) vpass_all()
{
    extern __shared__ char smv[];
    int z = blockIdx.z; int so = z/12; int img = z - so*12;
    switch (so){
        case 0: vpass_core<155>(5, img, smv, 10.f);  break;
        case 1: vpass_core<77 >(4, img, smv, 10.f);  break;
        case 2: vpass_core<39 >(3, img, smv, 20.f);  break;
        case 3: vpass_core<21 >(2, img, smv, 400.f); break;
        case 4: vpass_core<11 >(1, img, smv, 500.f); break;
        default:vpass_core<5  >(0, img, smv, 600.f); break;
    }
}

// ---- finalize ----
__global__ void final_kernel(float* out){
    double t = 0.0;
#pragma unroll
    for (int i = 0; i < 64; ++i) t += d_accv[i];
    out[0] = (float)(t * (1.0 / (double)NPIX));
}

extern "C" void kernel_launch(void* const* d_in, const int* in_sizes, int n_in,
                              void* d_out, int out_size)
{
    const float* input  = (const float*)d_in[0];
    const float* target = (const float*)d_in[1];
    float* out = (float*)d_out;

    // dynamic smem sizes (max across template branches = K=155)
    const int HS = (668 + 668/8 + 2)*16 + 160*16;            // 14608
    const int VS = (120 + 168)*16*8 + 168*8 + 64;            // 38272

    init_kernel<<<1, 256>>>();
    diff_prefix_kernel<<<dim3(512, NIMG), 256>>>(input, target);
    hpass_all<<<dim3(128, 1, 72), 128, HS>>>();
    vpass_all<<<dim3(32, 4, 72), 128, VS>>>();
    final_kernel<<<1, 1>>>(out);
}